// round 15
// baseline (speedup 1.0000x reference)
#include <cuda_runtime.h>
#include <cstdint>

// FMLayer: out[b, p] = wdot[p] * x[b, j1(p)] * x[b, j2(p)]
//   N_FEATURES = 512, K = 4, BATCH = 1024, P = 130816 (upper triangle, row-major by j1)
// DRAM-write-bound: 535.8 MB out per launch (~67 us floor @ 8 TB/s).
// Converged config (R10/R14: TPB=512, BT=4, __stcs, PDL) + one micro-opt:
// meta table transposed so each thread's 4 meta words are one LDG.128
// (per-thread table LDGs 8 -> 5; branch conditions in regs right after sync).

#define NF    512
#define BATCH 1024
#define NPAIR 130816              // 512*511/2
#define NQ4   (NPAIR / 4)         // 32704 float4 slots per batch row
#define BT    4                   // batch rows per block
#define TPB   512                 // threads per block
#define NCHUNK 16                 // chunks of 2048 float4 slots

// Scratch (allocation-free rule: __device__ globals; zero-initialized)
__device__ __align__(16) float g_wdot[NPAIR];
__device__ __align__(16) int   g_jidx[NPAIR];          // (j1<<16)|j2 per pair (slow path)
__device__ __align__(16) int   g_meta_t[NCHUNK * TPB * 4]; // transposed: [(c*512+t)*4 + u]

__device__ __forceinline__ int tri_off(int j) {
    return (NF - 1) * j - ((j * (j - 1)) >> 1);
}

// largest j1 with tri_off(j1) <= p ; j1 in [0,510] -> 9 branch-free steps, int-only
__device__ __forceinline__ int find_row(int p) {
    int lo = 0, hi = NF - 2;
    #pragma unroll
    for (int it = 0; it < 9; it++) {
        int mid = (lo + hi + 1) >> 1;
        if (tri_off(mid) <= p) lo = mid; else hi = mid - 1;
    }
    return lo;
}

// One thread per float4-slot q: recover (j1,j2) for p=4q, walk 4 pairs
// incrementally (exact row-crossing handling), emit wdot4/jidx4 + transposed meta.
__global__ void __launch_bounds__(256) fm_setup_kernel(const float* __restrict__ w) {
    int q = blockIdx.x * blockDim.x + threadIdx.x;
    if (q >= NQ4) return;

    int p  = 4 * q;
    int j1 = find_row(p);
    int j2 = p - tri_off(j1) + j1 + 1;

    const float4* w4 = reinterpret_cast<const float4*>(w);  // 8 KB, L1-resident
    float4 wa = __ldg(&w4[j1]);

    int   r1 = j1, r2 = j2;
    int   jj[4];
    float wdv[4];
    #pragma unroll
    for (int e = 0; e < 4; e++) {
        if (r2 >= NF) { r1++; r2 = r1 + 1; wa = __ldg(&w4[r1]); }
        float4 wb = __ldg(&w4[r2]);
        wdv[e] = wa.x * wb.x + wa.y * wb.y + wa.z * wb.z + wa.w * wb.w;
        jj[e]  = (r1 << 16) | r2;
        r2++;
    }

    reinterpret_cast<float4*>(g_wdot)[q] = make_float4(wdv[0], wdv[1], wdv[2], wdv[3]);
    reinterpret_cast<int4*>(g_jidx)[q]   = make_int4(jj[0], jj[1], jj[2], jj[3]);

    int meta = ((jj[0] >> 16) == (jj[3] >> 16)) ? jj[0] : -1;
    // transposed meta: chunk c = q>>11, within-chunk u = (q>>9)&3, lane t = q&511
    int c = q >> 11;
    int u = (q >> 9) & 3;
    int t = q & (TPB - 1);
    g_meta_t[((c * TPB + t) << 2) + u] = meta;
}

// Block = (chunk of 2048 float4 slots) x (BT=4 batch rows). 512 threads, 4 slots each.
// PDL: fill smem (table-independent), grid-sync, one int4 meta load, then stream.
__global__ void __launch_bounds__(TPB, 4) fm_main_kernel(
    const float* __restrict__ x, float* __restrict__ out)
{
    __shared__ float xs[BT][4][NF];   // xs[b][a][i] = x_row_b[a + i]; 32 KB

    const int b0 = blockIdx.y * BT;

    for (int i = threadIdx.x; i < BT * NF; i += TPB) {
        int bb = i >> 9;              // / NF
        int j  = i & (NF - 1);
        float v = x[(size_t)(b0 + bb) * NF + j];
        #pragma unroll
        for (int a = 0; a < 4; a++)
            if (j >= a) xs[bb][a][j - a] = v;
    }
    __syncthreads();

    // wait for fm_setup_kernel (PDL): tables valid beyond this point
    cudaGridDependencySynchronize();

    const int4*   jid4 = reinterpret_cast<const int4*>(g_jidx);
    const float4* wd4  = reinterpret_cast<const float4*>(g_wdot);
    float4* ob0 = reinterpret_cast<float4*>(out) + (size_t)b0 * NQ4;

    const int qbase = blockIdx.x * (TPB * 4) + threadIdx.x;

    // one LDG.128 fetches this thread's 4 meta words (transposed table)
    const int4 m4 = __ldg(&reinterpret_cast<const int4*>(g_meta_t)
                              [blockIdx.x * TPB + threadIdx.x]);
    const int mu_arr[4] = {m4.x, m4.y, m4.z, m4.w};

    #pragma unroll
    for (int u = 0; u < 4; u++) {
        int q = qbase + u * TPB;
        if (q >= NQ4) continue;       // only last chunk partially masked
        int    mu = mu_arr[u];
        float4 wv = __ldg(&wd4[q]);

        if (mu >= 0) {
            // fast path: all 4 pairs share j1, j2..j2+3 contiguous
            int j1  = mu >> 16;
            int j2s = mu & 0xffff;
            int a   = j2s & 3;
            int idx = (j2s - a) >> 2;
            #pragma unroll
            for (int bb = 0; bb < BT; bb++) {
                float  s  = xs[bb][0][j1];
                float4 xv = reinterpret_cast<const float4*>(xs[bb][a])[idx];
                float4 r;
                r.x = s * wv.x * xv.x;
                r.y = s * wv.y * xv.y;
                r.z = s * wv.z * xv.z;
                r.w = s * wv.w * xv.w;
                __stcs(&ob0[(size_t)bb * NQ4 + q], r);   // evict-first streaming store
            }
        } else {
            // slow path (1.6% of slots): row-crossing, per-element gather
            int4 j = __ldg(&jid4[q]);
            #pragma unroll
            for (int bb = 0; bb < BT; bb++) {
                const float* xr = xs[bb][0];
                float4 r;
                r.x = wv.x * xr[j.x >> 16] * xr[j.x & 0xffff];
                r.y = wv.y * xr[j.y >> 16] * xr[j.y & 0xffff];
                r.z = wv.z * xr[j.z >> 16] * xr[j.z & 0xffff];
                r.w = wv.w * xr[j.w >> 16] * xr[j.w & 0xffff];
                __stcs(&ob0[(size_t)bb * NQ4 + q], r);   // evict-first streaming store
            }
        }
    }
}

extern "C" void kernel_launch(void* const* d_in, const int* in_sizes, int n_in,
                              void* d_out, int out_size)
{
    const float* x = (const float*)d_in[0];   // [1024, 512]
    const float* w = (const float*)d_in[1];   // [512, 4]
    float* out = (float*)d_out;               // [1024, 130816]
    (void)in_sizes; (void)n_in; (void)out_size;

    fm_setup_kernel<<<(NQ4 + 255) / 256, 256>>>(w);

    // PDL launch: main kernel's blocks may start before setup completes;
    // they grid-sync before touching the tables.
    dim3 grid(NCHUNK, BATCH / BT);   // 16 * 2048 f4 = 32768 >= 32704 (guarded)

    cudaLaunchConfig_t cfg = {};
    cfg.gridDim  = grid;
    cfg.blockDim = dim3(TPB, 1, 1);
    cfg.dynamicSmemBytes = 0;
    cfg.stream = 0;
    cudaLaunchAttribute attrs[1];
    attrs[0].id = cudaLaunchAttributeProgrammaticStreamSerialization;
    attrs[0].val.programmaticStreamSerializationAllowed = 1;
    cfg.attrs = attrs;
    cfg.numAttrs = 1;
    cudaLaunchKernelEx(&cfg, fm_main_kernel, x, out);
}